// round 17
// baseline (speedup 1.0000x reference)
#include <cuda_runtime.h>
#include <cuda_fp16.h>
#include <cstdint>

#define H_DIM 1024
#define S_DIM 2048
#define B_DIM 32
#define M_TILE 128
#define N_PASS 256
#define KC 64
#define NUM_G 64            // 4 passes x 16 K-chunks, continuous pipeline
#define NT 512              // 16 warps = 4 per SMSP

// smem layout
#define SMEM_DVEC 0
#define SMEM_VA   4096
#define SMEM_SCORE 8192     // 128 floats
#define SMEM_STAGES 9216
#define STAGE_SZ  49152     // A fp16 16KB + B fp16 32KB
#define SMEM_B_OFF 16384
#define SMEM_F32  (SMEM_STAGES + 3 * STAGE_SZ)    // 156672: 2 x 32KB fp32 A staging
#define F32_SZ    32768
#define SMEM_TOTAL (SMEM_F32 + 2 * F32_SZ)        // 222208 <= 232448 opt-in

__device__ __align__(16) __half g_ut[(size_t)H_DIM * H_DIM];          // Ua^T fp16, 2MB
__device__ float g_dvec[B_DIM * H_DIM];

__device__ __forceinline__ uint32_t smem_u32(const void* p) {
    uint32_t a;
    asm("{ .reg .u64 t; cvta.to.shared.u64 t, %1; cvt.u32.u64 %0, t; }" : "=r"(a) : "l"(p));
    return a;
}
__device__ __forceinline__ void cp16(uint32_t s, const void* g) {
    asm volatile("cp.async.cg.shared.global [%0], [%1], 16;" :: "r"(s), "l"(g));
}
#define CP_COMMIT() asm volatile("cp.async.commit_group;" ::: "memory")
#define CP_WAIT0()  asm volatile("cp.async.wait_group 0;" ::: "memory")
#define STS128(a, r0, r1, r2, r3) \
    asm volatile("st.shared.v4.b32 [%0], {%1,%2,%3,%4};" \
                 :: "r"(a), "r"(r0), "r"(r1), "r"(r2), "r"(r3))

__device__ __forceinline__ void ldm4(uint32_t& r0, uint32_t& r1, uint32_t& r2, uint32_t& r3,
                                     uint32_t a) {
    asm volatile("ldmatrix.sync.aligned.m8n8.x4.shared.b16 {%0,%1,%2,%3}, [%4];"
                 : "=r"(r0), "=r"(r1), "=r"(r2), "=r"(r3) : "r"(a));
}
__device__ __forceinline__ void mma16816(float* c, const uint32_t* a, uint32_t b0, uint32_t b1) {
    asm volatile("mma.sync.aligned.m16n8k16.row.col.f32.f16.f16.f32 "
                 "{%0,%1,%2,%3}, {%4,%5,%6,%7}, {%8,%9}, {%0,%1,%2,%3};"
                 : "+f"(c[0]), "+f"(c[1]), "+f"(c[2]), "+f"(c[3])
                 : "r"(a[0]), "r"(a[1]), "r"(a[2]), "r"(a[3]), "r"(b0), "r"(b1));
}

// FMA/ALU-only tanh (no MUFU): exp2 range reduction + deg-5 poly + Newton rcp. abs err ~3e-5.
__device__ __forceinline__ float fast_tanh(float x) {
    x = fminf(9.0f, fmaxf(-9.0f, x));
    const float C = 2.885390082f;
    float zm = fmaf(x, C, 12582912.0f);
    int nb = __float_as_int(zm);
    float nf = zm - 12582912.0f;
    float f = fmaf(x, C, -nf);
    float p = 1.3333558e-3f;
    p = fmaf(p, f, 9.6181291e-3f);
    p = fmaf(p, f, 5.5504109e-2f);
    p = fmaf(p, f, 2.4022651e-1f);
    p = fmaf(p, f, 6.9314718e-1f);
    p = fmaf(p, f, 1.0f);
    float E = p * __int_as_float((nb + (127 - 0x4B400000)) << 23);
    float D = E + 1.0f;
    float r = __int_as_float((int)(0x7EF127EAu - (uint32_t)__float_as_int(D)));
    r = r * fmaf(-D, r, 2.0f);
    r = r * fmaf(-D, r, 2.0f);
    r = r * fmaf(-D, r, 2.0f);
    return fmaf(-2.0f, r, 1.0f);
}

// pack 8 fp32 -> 4 half2 regs and STS128
__device__ __forceinline__ void cvt_sts(uint32_t dst, float4 v0, float4 v1) {
    __half2 h0 = __floats2half2_rn(v0.x, v0.y);
    __half2 h1 = __floats2half2_rn(v0.z, v0.w);
    __half2 h2 = __floats2half2_rn(v1.x, v1.y);
    __half2 h3 = __floats2half2_rn(v1.z, v1.w);
    STS128(dst, *(uint32_t*)&h0, *(uint32_t*)&h1, *(uint32_t*)&h2, *(uint32_t*)&h3);
}

// ---------------- Ut[k][h] = Ua[h][k] as fp16 ----------------
__global__ void ut_split_kernel(const float* __restrict__ ua_w) {
    __shared__ float tile[32][33];
    int tx = threadIdx.x, ty = threadIdx.y;
    int k = blockIdx.x * 32 + tx, h0 = blockIdx.y * 32;
    #pragma unroll
    for (int i = 0; i < 32; i += 8)
        tile[ty + i][tx] = ua_w[(size_t)(h0 + ty + i) * H_DIM + k];
    __syncthreads();
    #pragma unroll
    for (int i = 0; i < 32; i += 8) {
        int kk = blockIdx.x * 32 + ty + i;
        g_ut[(size_t)kk * H_DIM + h0 + tx] = __float2half(tile[tx][ty + i]);
    }
}

// ---------------- dvec[b,k] = Wa_b[k]+Ua_b[k] + sum_h dec[b,h]*Wa[h,k] ----------------
__global__ void __launch_bounds__(256) dvec_kernel(
    const float* __restrict__ dec, const float* __restrict__ wa_w,
    const float* __restrict__ wa_b, const float* __restrict__ ua_b) {
    __shared__ float ds[H_DIM];
    int b = blockIdx.x >> 2, kc = blockIdx.x & 3, tid = threadIdx.x;
    #pragma unroll
    for (int i = 0; i < 4; ++i) ds[tid + i * 256] = dec[b * H_DIM + tid + i * 256];
    __syncthreads();
    int k = kc * 256 + tid;
    float acc = wa_b[k] + ua_b[k];
    #pragma unroll 8
    for (int h = 0; h < H_DIM; ++h) acc += ds[h] * __ldg(&wa_w[(size_t)h * H_DIM + k]);
    g_dvec[b * H_DIM + k] = acc;
}

// ---------------- fused GEMM (512 thr) + in-loop fp32->fp16 A + tanh + Va-dot ----------------
// M128 x N256; B via cp.async fp16; A via cp.async fp32 -> smem staging -> convert -> fp16 stage.
__global__ void __launch_bounds__(NT, 1) gemm_kernel(
    const float* __restrict__ enc, const float* __restrict__ va_w,
    float* __restrict__ scores) {
    extern __shared__ __align__(128) char smem[];
    uint32_t sb = smem_u32(smem);
    int tid = threadIdx.x, lane = tid & 31, wid = tid >> 5;
    int warp_m = wid >> 2, warp_n = wid & 3;     // 4 x 4 warps: M32, N64 each
    int m0 = blockIdx.x * M_TILE;
    int bidx = m0 >> 11;

    if (tid < 256) {
        ((float4*)(smem + SMEM_DVEC))[tid] = ((const float4*)(g_dvec + bidx * H_DIM))[tid];
        ((float4*)(smem + SMEM_VA))[tid] = ((const float4*)va_w)[tid];
    }
    float* s_score = (float*)(smem + SMEM_SCORE);
    if (tid < M_TILE) s_score[tid] = 0.f;
    const float* smd = (const float*)(smem + SMEM_DVEC);
    const float* smv = (const float*)(smem + SMEM_VA);

    // hoisted ldmatrix addressing
    int r8 = lane & 7, sel = lane >> 3;
    int selb = (sel & 1) << 3, selc = sel >> 1;
    uint32_t aOff = (uint32_t)((warp_m * 32 + selb + r8) * 128);
    uint32_t bOff = (uint32_t)((warp_n * 64 + selb + r8) * 128);
    uint32_t csw[4];
    #pragma unroll
    for (int ks = 0; ks < 4; ++ks) csw[ks] = (uint32_t)(((ks * 2 + selc) ^ r8) << 4);

    // hoisted fill addressing: A 1024 slots (2/thread), B 2048 slots (4/thread)
    int arow[2], aswf[2], ach[2], af32[2];
    #pragma unroll
    for (int i = 0; i < 2; ++i) {
        int idx = tid + i * NT;
        arow[i] = idx >> 3; ach[i] = idx & 7;
        aswf[i] = arow[i] * 128 + ((ach[i] ^ (arow[i] & 7)) << 4);
        af32[i] = arow[i] * 256 + ach[i] * 32;      // linear fp32 staging layout
    }
    int brow[4], bswf[4], bch[4];
    #pragma unroll
    for (int i = 0; i < 4; ++i) {
        int idx = tid + i * NT;
        brow[i] = idx >> 3; bch[i] = idx & 7;
        bswf[i] = SMEM_B_OFF + brow[i] * 128 + ((bch[i] ^ (brow[i] & 7)) << 4);
    }

    uint32_t stg[3];
    stg[0] = sb + SMEM_STAGES; stg[1] = stg[0] + STAGE_SZ; stg[2] = stg[1] + STAGE_SZ;
    uint32_t f32b[2];
    f32b[0] = sb + SMEM_F32; f32b[1] = f32b[0] + F32_SZ;

    float acc[2][8][4] = {};
    float partial[4] = {};

    // ---- prologue ----
    // fp16 A chunks 0,1: direct LDG+convert+STS (transient regs only)
    #pragma unroll
    for (int g = 0; g < 2; ++g) {
        int k0 = g * KC;
        #pragma unroll
        for (int i = 0; i < 2; ++i) {
            const float4* s = (const float4*)(enc + (size_t)(m0 + arow[i]) * H_DIM + k0 + ach[i] * 8);
            cvt_sts(stg[g] + aswf[i], s[0], s[1]);
        }
    }
    // B chunks 0,1 (groups 1,2) + fp32 A chunk 2 into staging buf 0 (group 2)
    #pragma unroll
    for (int g = 0; g < 2; ++g) {
        int k0 = g * KC;
        #pragma unroll
        for (int i = 0; i < 4; ++i)
            cp16(stg[g] + bswf[i], g_ut + (size_t)brow[i] * H_DIM + k0 + bch[i] * 8);
        if (g == 1) {
            #pragma unroll
            for (int i = 0; i < 2; ++i) {
                const float* s = enc + (size_t)(m0 + arow[i]) * H_DIM + 2 * KC + ach[i] * 8;
                cp16(f32b[0] + af32[i], s);
                cp16(f32b[0] + af32[i] + 16, s + 4);
            }
        }
        CP_COMMIT();
    }

    // ---- main: 64 chunks, one barrier per chunk, 3-stage pipeline ----
    for (int g = 0; g < NUM_G; ++g) {
        CP_WAIT0();
        __syncthreads();   // orders prologue/convert STS + cp.async visibility

        // issue next fills: B fp16 for chunk g+2, fp32 A for chunk g+3
        int gf = g + 2;
        if (gf < NUM_G) {
            int k0f = (gf & 15) * KC;
            int n0f = (gf >> 4) * N_PASS;
            uint32_t stf = stg[gf % 3];
            #pragma unroll
            for (int i = 0; i < 4; ++i)
                cp16(stf + bswf[i], g_ut + (size_t)(n0f + brow[i]) * H_DIM + k0f + bch[i] * 8);
        }
        int ga = g + 3;
        if (ga < NUM_G) {
            int k0a = (ga & 15) * KC;
            uint32_t fb = f32b[ga & 1];
            #pragma unroll
            for (int i = 0; i < 2; ++i) {
                const float* s = enc + (size_t)(m0 + arow[i]) * H_DIM + k0a + ach[i] * 8;
                cp16(fb + af32[i], s);
                cp16(fb + af32[i] + 16, s + 4);
            }
        }
        CP_COMMIT();

        // compute current chunk
        uint32_t sA = stg[g % 3] + aOff, sB = stg[g % 3] + SMEM_B_OFF + bOff;
        #pragma unroll
        for (int ks = 0; ks < 4; ++ks) {
            uint32_t aAdr = sA + csw[ks], bAdr = sB + csw[ks];
            uint32_t a[2][4], b[4][4];
            #pragma unroll
            for (int mf = 0; mf < 2; ++mf)
                ldm4(a[mf][0], a[mf][1], a[mf][2], a[mf][3], aAdr + mf * 2048);
            #pragma unroll
            for (int nf2 = 0; nf2 < 4; ++nf2)
                ldm4(b[nf2][0], b[nf2][1], b[nf2][2], b[nf2][3], bAdr + nf2 * 2048);
            #pragma unroll
            for (int mf = 0; mf < 2; ++mf)
                #pragma unroll
                for (int nf = 0; nf < 8; ++nf)
                    mma16816(acc[mf][nf], a[mf], b[nf >> 1][nf & 1], b[nf >> 1][(nf & 1) + 2]);
        }

        // convert staged fp32 A of chunk g+2 -> fp16 stage (transient regs; drained by barrier g+1)
        if (gf < NUM_G) {
            uint32_t fb = f32b[gf & 1];
            uint32_t stf = stg[gf % 3];
            #pragma unroll
            for (int i = 0; i < 2; ++i) {
                float4 v0 = *(const float4*)(smem + (fb - sb) + af32[i]);
                float4 v1 = *(const float4*)(smem + (fb - sb) + af32[i] + 16);
                cvt_sts(stf + aswf[i], v0, v1);
            }
        }

        // per-pass epilogue: tanh(acc + dvec) . Va, reset accumulators
        if ((g & 15) == 15) {
            int n0 = (g >> 4) * N_PASS;
            #pragma unroll
            for (int nf = 0; nf < 8; ++nf) {
                int col = n0 + warp_n * 64 + nf * 8 + (lane & 3) * 2;
                float dx = smd[col], dy = smd[col + 1];
                float vx = smv[col], vy = smv[col + 1];
                #pragma unroll
                for (int mf = 0; mf < 2; ++mf) {
                    float* c = acc[mf][nf];
                    partial[mf * 2 + 0] += vx * fast_tanh(c[0] + dx) + vy * fast_tanh(c[1] + dy);
                    partial[mf * 2 + 1] += vx * fast_tanh(c[2] + dx) + vy * fast_tanh(c[3] + dy);
                    c[0] = c[1] = c[2] = c[3] = 0.f;
                }
            }
        }
    }

    // reduce per-thread partials -> per-row scores
    #pragma unroll
    for (int p = 0; p < 4; ++p) {
        float v = partial[p];
        v += __shfl_xor_sync(0xFFFFFFFFu, v, 1);
        v += __shfl_xor_sync(0xFFFFFFFFu, v, 2);
        if ((lane & 3) == 0) {
            int row = warp_m * 32 + (p >> 1) * 16 + (p & 1) * 8 + (lane >> 2);
            atomicAdd(&s_score[row], v);
        }
    }
    __syncthreads();
    if (tid < M_TILE) scores[m0 + tid] = s_score[tid];
}

// ---------------- masked softmax over S, in place ----------------
__global__ void __launch_bounds__(256) softmax_kernel(
    const int* __restrict__ mask, float* __restrict__ out) {
    __shared__ float red[8];
    int b = blockIdx.x, tid = threadIdx.x, wid = tid >> 5, lid = tid & 31;
    float v[8], mx = -3.0e38f;
    #pragma unroll
    for (int i = 0; i < 8; ++i) {
        int s = tid + i * 256;
        float x = out[b * S_DIM + s];
        if (mask[b * S_DIM + s] == 0) x = -1e9f;
        v[i] = x; mx = fmaxf(mx, x);
    }
    #pragma unroll
    for (int o = 16; o > 0; o >>= 1) mx = fmaxf(mx, __shfl_xor_sync(0xFFFFFFFFu, mx, o));
    if (lid == 0) red[wid] = mx;
    __syncthreads();
    mx = red[0];
    #pragma unroll
    for (int w = 1; w < 8; ++w) mx = fmaxf(mx, red[w]);
    float sum = 0.f;
    #pragma unroll
    for (int i = 0; i < 8; ++i) { v[i] = expf(v[i] - mx); sum += v[i]; }
    #pragma unroll
    for (int o = 16; o > 0; o >>= 1) sum += __shfl_xor_sync(0xFFFFFFFFu, sum, o);
    __syncthreads();
    if (lid == 0) red[wid] = sum;
    __syncthreads();
    sum = 0.f;
    #pragma unroll
    for (int w = 0; w < 8; ++w) sum += red[w];
    float inv = 1.f / sum;
    #pragma unroll
    for (int i = 0; i < 8; ++i) out[b * S_DIM + tid + i * 256] = v[i] * inv;
}

extern "C" void kernel_launch(void* const* d_in, const int* in_sizes, int n_in,
                              void* d_out, int out_size) {
    const float* dec  = (const float*)d_in[0];
    const float* enc  = (const float*)d_in[1];
    const int*   mask = (const int*)d_in[2];
    const float* wa_w = (const float*)d_in[3];
    const float* wa_b = (const float*)d_in[4];
    const float* ua_w = (const float*)d_in[5];
    const float* ua_b = (const float*)d_in[6];
    const float* va_w = (const float*)d_in[7];
    float* out = (float*)d_out;

    cudaFuncSetAttribute(gemm_kernel, cudaFuncAttributeMaxDynamicSharedMemorySize, SMEM_TOTAL);

    ut_split_kernel<<<dim3(32, 32), dim3(32, 8)>>>(ua_w);
    dvec_kernel<<<B_DIM * 4, 256>>>(dec, wa_w, wa_b, ua_b);
    gemm_kernel<<<(B_DIM * S_DIM) / M_TILE, NT, SMEM_TOTAL>>>(enc, va_w, out);
    softmax_kernel<<<B_DIM, 256>>>(mask, out);
}